// round 12
// baseline (speedup 1.0000x reference)
#include <cuda_runtime.h>
#include <cuda_fp16.h>
#include <math.h>
#include <stdint.h>

#define N_TOK 4096      // B*S
#define DDIM  1024      // D
#define FDIM  4096      // F
#define NEXP  8         // E
#define LN_EPS 1e-5f

#define BM 128
#define BN 128
#define BK 32
#define ROWB 80                  // smem bytes per row: 32 fp16 + 8 pad
#define ATILE (128 * ROWB)       // 10240 B per operand tile
#define STAGEB (3 * ATILE)       // Ah, Al, B = 30720 B per stage
#define NSTAGE 3
#define SMEM_BYTES (NSTAGE * STAGEB)  // 92160 B

// ---- static device scratch (no runtime allocation allowed) ----
__device__ int   g_counts[NEXP];
__device__ int   g_rows[NEXP * N_TOK];          // value = token*2 + slot
__device__ float g_slotw[2 * N_TOK];            // softmax weight per slot
__device__ __half g_Xhi[N_TOK * DDIM];
__device__ __half g_Xlo[N_TOK * DDIM];
__device__ __half g_W1[NEXP * FDIM * DDIM];     // weights: single fp16
__device__ __half g_W2[NEXP * DDIM * FDIM];
__device__ __half g_Hhi[(size_t)2 * N_TOK * FDIM];
__device__ __half g_Hlo[(size_t)2 * N_TOK * FDIM];
__device__ float g_Y[(size_t)2 * N_TOK * DDIM]; // [8192][1024] H@W2^T+b2 (unweighted)

// ============================ PTX helpers ============================
static __device__ __forceinline__ void cp16(uint32_t s, const void* g) {
    asm volatile("cp.async.cg.shared.global [%0], [%1], 16;" :: "r"(s), "l"(g));
}

#define LDSM4(r0, r1, r2, r3, addr)                                           \
    asm volatile("ldmatrix.sync.aligned.m8n8.x4.shared.b16 {%0,%1,%2,%3}, [%4];" \
                 : "=r"(r0), "=r"(r1), "=r"(r2), "=r"(r3) : "r"(addr))

// fp16 inputs, fp32 accumulators (main term)
#define MMAF32(d, a, b0, b1)                                                  \
    asm volatile("mma.sync.aligned.m16n8k16.row.col.f32.f16.f16.f32 "         \
                 "{%0,%1,%2,%3}, {%4,%5,%6,%7}, {%8,%9}, {%0,%1,%2,%3};"      \
                 : "+f"((d)[0]), "+f"((d)[1]), "+f"((d)[2]), "+f"((d)[3])     \
                 : "r"((a)[0]), "r"((a)[1]), "r"((a)[2]), "r"((a)[3]),        \
                   "r"(b0), "r"(b1))

// fp16 inputs, fp16 accumulators (correction term)
#define MMAF16(d, a, b0, b1)                                                  \
    asm volatile("mma.sync.aligned.m16n8k16.row.col.f16.f16.f16.f16 "         \
                 "{%0,%1}, {%2,%3,%4,%5}, {%6,%7}, {%0,%1};"                  \
                 : "+r"((d)[0]), "+r"((d)[1])                                 \
                 : "r"((a)[0]), "r"((a)[1]), "r"((a)[2]), "r"((a)[3]),        \
                   "r"(b0), "r"(b1))

// ============================ small kernels ============================
__global__ void init_counts_kernel() {
    if (threadIdx.x < NEXP) g_counts[threadIdx.x] = 0;
}

// fp32 -> fp16 hi/lo split (activations)
__global__ void split_fp16_kernel(const float* __restrict__ src,
                                  __half* __restrict__ hi,
                                  __half* __restrict__ lo, int n) {
    int i = (blockIdx.x * blockDim.x + threadIdx.x) * 4;
    if (i >= n) return;
    float4 v = *(const float4*)(src + i);
    float vv[4] = {v.x, v.y, v.z, v.w};
    __half h[4], l[4];
#pragma unroll
    for (int j = 0; j < 4; j++) {
        h[j] = __float2half_rn(vv[j]);
        l[j] = __float2half_rn(vv[j] - __half2float(h[j]));
    }
    __half2 h0; h0.x = h[0]; h0.y = h[1];
    __half2 h1; h1.x = h[2]; h1.y = h[3];
    __half2 l0; l0.x = l[0]; l0.y = l[1];
    __half2 l1; l1.x = l[2]; l1.y = l[3];
    *(__half2*)(hi + i)     = h0;
    *(__half2*)(hi + i + 2) = h1;
    *(__half2*)(lo + i)     = l0;
    *(__half2*)(lo + i + 2) = l1;
}

// fp32 -> fp16 single convert (weights)
__global__ void cvt_fp16_kernel(const float* __restrict__ src,
                                __half* __restrict__ dst, int n) {
    int i = (blockIdx.x * blockDim.x + threadIdx.x) * 4;
    if (i >= n) return;
    float4 v = *(const float4*)(src + i);
    __half2 a; a.x = __float2half_rn(v.x); a.y = __float2half_rn(v.y);
    __half2 b; b.x = __float2half_rn(v.z); b.y = __float2half_rn(v.w);
    *(__half2*)(dst + i)     = a;
    *(__half2*)(dst + i + 2) = b;
}

// One warp per token: 8 logits, top-2, softmax, append to expert lists.
__global__ void router_kernel(const float* __restrict__ tgt,
                              const float* __restrict__ Wr,
                              const float* __restrict__ br) {
    int token = blockIdx.x * 8 + (threadIdx.x >> 5);
    int lane  = threadIdx.x & 31;
    if (token >= N_TOK) return;

    const float* x = tgt + (size_t)token * DDIM;
    float xr[32];
#pragma unroll
    for (int i = 0; i < 32; i++) xr[i] = x[lane + 32 * i];

    float logits[NEXP];
#pragma unroll
    for (int e = 0; e < NEXP; e++) {
        const float* w = Wr + e * DDIM;
        float s = 0.f;
#pragma unroll
        for (int i = 0; i < 32; i++) s += xr[i] * w[lane + 32 * i];
#pragma unroll
        for (int o = 16; o > 0; o >>= 1) s += __shfl_xor_sync(0xffffffffu, s, o);
        logits[e] = s + br[e];
    }

    if (lane == 0) {
        int i0 = 0; float v0 = logits[0];
#pragma unroll
        for (int e = 1; e < NEXP; e++) if (logits[e] > v0) { v0 = logits[e]; i0 = e; }
        int i1 = -1; float v1 = -INFINITY;
#pragma unroll
        for (int e = 0; e < NEXP; e++) if (e != i0 && logits[e] > v1) { v1 = logits[e]; i1 = e; }
        float e1  = expf(v1 - v0);
        float inv = 1.f / (1.f + e1);
        g_slotw[2 * token]     = inv;
        g_slotw[2 * token + 1] = e1 * inv;
        int p0 = atomicAdd(&g_counts[i0], 1); g_rows[i0 * N_TOK + p0] = 2 * token;
        int p1 = atomicAdd(&g_counts[i1], 1); g_rows[i1 * N_TOK + p1] = 2 * token + 1;
    }
}

// ============================ mma.sync grouped GEMM ============================
// C[m][n] = sum_k A[m][k]*B[n][k], A split fp16 hi+lo, B single fp16:
//   accM(fp32) += Ah*B ;  accC(fp16) += Al*B ;  C = accM + accC
// 512 thr = 16 warps (4 M x 4 N), warp tile 32x32, block tile 128x128, BK=32.
// 3-stage cp.async ring, ONE __syncthreads per K-chunk.
__global__ void __launch_bounds__(512, 1)
mma_gemm_kernel(int is_gemm1, int Ndim, int Kdim, const float* __restrict__ bias) {
    extern __shared__ __align__(128) char smem[];
    uint32_t sb = (uint32_t)__cvta_generic_to_shared(smem);

    int e  = blockIdx.z;
    int nt = blockIdx.y;
    int mt = blockIdx.x;     // mt fastest -> concurrent blocks share weight tile (L2)
    int cnt = g_counts[e];
    if (mt * BM >= cnt) return;

    const int* erows = g_rows + e * N_TOK;
    const __half *Ahb, *Alb, *Wb;
    if (is_gemm1) { Ahb = g_Xhi; Alb = g_Xlo; Wb = g_W1; }
    else          { Ahb = g_Hhi; Alb = g_Hlo; Wb = g_W2; }

    int tid = threadIdx.x;

    // ---- global->smem geometry: thread -> (row = tid>>2, 16B seg = tid&3) ----
    int lrow = tid >> 2;
    int seg  = tid & 3;
    int kb   = seg * 8;                      // element offset of this thread's 16B
    int mr_l = mt * BM + lrow; if (mr_l > cnt - 1) mr_l = cnt - 1;
    int arow = erows[mr_l]; if (is_gemm1) arow >>= 1;
    const __half* aph = Ahb + (size_t)arow * Kdim + kb;
    const __half* apl = Alb + (size_t)arow * Kdim + kb;
    const __half* bpw = Wb + ((size_t)e * Ndim + nt * BN + lrow) * Kdim + kb;
    uint32_t dst = (uint32_t)lrow * ROWB + seg * 16;

    // ---- fragment (ldmatrix) geometry ----
    int lane = tid & 31, wid = tid >> 5;
    int wm = wid & 3, wn = wid >> 2;         // warp tile origin (wm*32, wn*32)
    uint32_t afa = (uint32_t)(wm * 32 + (lane & 15)) * ROWB + (lane >> 4) * 16;
    uint32_t bfa = (uint32_t)(wn * 32 + (lane & 15)) * ROWB + (lane >> 4) * 16;

    float    accM[2][4][4];
    uint32_t accC[2][4][2];
#pragma unroll
    for (int mi = 0; mi < 2; mi++)
#pragma unroll
        for (int ni = 0; ni < 4; ni++) {
#pragma unroll
            for (int r = 0; r < 4; r++) accM[mi][ni][r] = 0.f;
            accC[mi][ni][0] = 0u; accC[mi][ni][1] = 0u;
        }

    auto issue = [&](int i) {
        uint32_t d = sb + (uint32_t)(i % NSTAGE) * STAGEB + dst;
        size_t ko = (size_t)i * BK;
        cp16(d,              aph + ko);
        cp16(d + ATILE,      apl + ko);
        cp16(d + 2 * ATILE,  bpw + ko);
        asm volatile("cp.async.commit_group;" ::: "memory");
    };

    int nch = Kdim / BK;
    issue(0);
    if (nch > 1) issue(1);
    for (int i = 0; i < nch; i++) {
        if (i + 1 < nch) {
            asm volatile("cp.async.wait_group 1;" ::: "memory");
        } else {
            asm volatile("cp.async.wait_group 0;" ::: "memory");
        }
        __syncthreads();   // chunk i visible; stage (i+2)%3 free for reuse
        if (i + 2 < nch) issue(i + 2);

        uint32_t bb = sb + (uint32_t)(i % NSTAGE) * STAGEB;
#pragma unroll
        for (int s = 0; s < 2; s++) {        // two k16 steps per chunk
            uint32_t aA = bb + afa + s * 32;             // Ah (then Al)
            uint32_t aB = bb + 2 * ATILE + bfa + s * 32; // B (weights)
            uint32_t af[2][4], bf[2][4];

            // Ah fragments (2) + B fragments (2)
#pragma unroll
            for (int mi = 0; mi < 2; mi++)
                LDSM4(af[mi][0], af[mi][1], af[mi][2], af[mi][3], aA + mi * 16 * ROWB);
#pragma unroll
            for (int nj = 0; nj < 2; nj++)
                LDSM4(bf[nj][0], bf[nj][1], bf[nj][2], bf[nj][3], aB + nj * 16 * ROWB);

            // main: Ah * B -> fp32 accum
#pragma unroll
            for (int mi = 0; mi < 2; mi++)
#pragma unroll
                for (int ni = 0; ni < 4; ni++)
                    MMAF32(accM[mi][ni], af[mi],
                           bf[ni >> 1][ni & 1], bf[ni >> 1][(ni & 1) + 2]);

            // Al fragments overwrite Ah slots (2)
#pragma unroll
            for (int mi = 0; mi < 2; mi++)
                LDSM4(af[mi][0], af[mi][1], af[mi][2], af[mi][3],
                      aA + ATILE + mi * 16 * ROWB);

            // corr: Al * B -> fp16 accum
#pragma unroll
            for (int mi = 0; mi < 2; mi++)
#pragma unroll
                for (int ni = 0; ni < 4; ni++)
                    MMAF16(accC[mi][ni], af[mi],
                           bf[ni >> 1][ni & 1], bf[ni >> 1][(ni & 1) + 2]);
        }
    }

    // ---- epilogue ----
    int tg = lane >> 2, tc = (lane & 3) * 2;
    const float* bbias = bias + e * Ndim + nt * BN;
    float bias_r[8];
#pragma unroll
    for (int ni = 0; ni < 4; ni++) {
        int c = wn * 32 + ni * 8 + tc;
        bias_r[2 * ni]     = __ldg(bbias + c);
        bias_r[2 * ni + 1] = __ldg(bbias + c + 1);
    }
#pragma unroll
    for (int mi = 0; mi < 2; mi++) {
#pragma unroll
        for (int half = 0; half < 2; half++) {
            int r = wm * 32 + mi * 16 + tg + half * 8;
            int mr = mt * BM + r;
            if (mr < cnt) {
                int orow = erows[mr];
#pragma unroll
                for (int ni = 0; ni < 4; ni++) {
                    int c = wn * 32 + ni * 8 + tc;
                    __half2 hc = *reinterpret_cast<__half2*>(&accC[mi][ni][half]);
                    float v0 = accM[mi][ni][half * 2]     + __low2float(hc)  + bias_r[2 * ni];
                    float v1 = accM[mi][ni][half * 2 + 1] + __high2float(hc) + bias_r[2 * ni + 1];
                    int n = nt * BN + c;
                    if (is_gemm1) {
                        v0 = fmaxf(v0, 0.f); v1 = fmaxf(v1, 0.f);
                        __half h0 = __float2half_rn(v0);
                        __half h1 = __float2half_rn(v1);
                        __half2 hh; hh.x = h0; hh.y = h1;
                        __half2 ll;
                        ll.x = __float2half_rn(v0 - __half2float(h0));
                        ll.y = __float2half_rn(v1 - __half2float(h1));
                        *(__half2*)(g_Hhi + (size_t)orow * FDIM + n) = hh;
                        *(__half2*)(g_Hlo + (size_t)orow * FDIM + n) = ll;
                    } else {
                        float2 t; t.x = v0; t.y = v1;
                        *(float2*)(g_Y + (size_t)orow * DDIM + n) = t;
                    }
                }
            }
        }
    }
}

// ============================ LN ============================
__global__ void ln_kernel(const float* __restrict__ tgt,
                          const float* __restrict__ gamma,
                          const float* __restrict__ beta,
                          float* __restrict__ out) {
    int token = blockIdx.x;
    int tid = threadIdx.x;
    __shared__ float red[8];

    float w0 = g_slotw[2 * token], w1 = g_slotw[2 * token + 1];
    const float* x  = tgt + (size_t)token * DDIM;
    const float* y0 = g_Y + (size_t)(2 * token) * DDIM;
    const float* y1 = y0 + DDIM;

    float v[4];
    float s = 0.f;
#pragma unroll
    for (int i = 0; i < 4; i++) {
        int d = tid + 256 * i;
        v[i] = x[d] + w0 * y0[d] + w1 * y1[d];
        s += v[i];
    }
#pragma unroll
    for (int o = 16; o > 0; o >>= 1) s += __shfl_xor_sync(0xffffffffu, s, o);
    if ((tid & 31) == 0) red[tid >> 5] = s;
    __syncthreads();
    float mu = (red[0] + red[1] + red[2] + red[3] + red[4] + red[5] + red[6] + red[7]) * (1.f / DDIM);

    float sq = 0.f;
#pragma unroll
    for (int i = 0; i < 4; i++) { float dv = v[i] - mu; sq += dv * dv; }
#pragma unroll
    for (int o = 16; o > 0; o >>= 1) sq += __shfl_xor_sync(0xffffffffu, sq, o);
    __syncthreads();
    if ((tid & 31) == 0) red[tid >> 5] = sq;
    __syncthreads();
    float var = (red[0] + red[1] + red[2] + red[3] + red[4] + red[5] + red[6] + red[7]) * (1.f / DDIM);
    float inv = rsqrtf(var + LN_EPS);

#pragma unroll
    for (int i = 0; i < 4; i++) {
        int d = tid + 256 * i;
        out[(size_t)token * DDIM + d] = (v[i] - mu) * inv * gamma[d] + beta[d];
    }
}

// ============================ launch ============================
extern "C" void kernel_launch(void* const* d_in, const int* in_sizes, int n_in,
                              void* d_out, int out_size) {
    const float* tgt   = (const float*)d_in[0];
    const float* Wr    = (const float*)d_in[1];
    const float* br    = (const float*)d_in[2];
    const float* W1    = (const float*)d_in[3];
    const float* b1    = (const float*)d_in[4];
    const float* W2    = (const float*)d_in[5];
    const float* b2    = (const float*)d_in[6];
    const float* gamma = (const float*)d_in[7];
    const float* beta  = (const float*)d_in[8];
    float* out = (float*)d_out;

    cudaFuncSetAttribute(mma_gemm_kernel,
                         cudaFuncAttributeMaxDynamicSharedMemorySize, SMEM_BYTES);

    init_counts_kernel<<<1, 32>>>();
    router_kernel<<<N_TOK / 8, 256>>>(tgt, Wr, br);

    // activation split + weight convert
    {
        __half *xh, *xl, *w1p, *w2p;
        cudaGetSymbolAddress((void**)&xh,  g_Xhi);
        cudaGetSymbolAddress((void**)&xl,  g_Xlo);
        cudaGetSymbolAddress((void**)&w1p, g_W1);
        cudaGetSymbolAddress((void**)&w2p, g_W2);
        int nx = N_TOK * DDIM;              // 4,194,304
        int nw = NEXP * FDIM * DDIM;        // 33,554,432
        split_fp16_kernel<<<nx / 1024, 256>>>(tgt, xh, xl, nx);
        cvt_fp16_kernel<<<nw / 1024, 256>>>(W1, w1p, nw);
        cvt_fp16_kernel<<<nw / 1024, 256>>>(W2, w2p, nw);
    }

    // GEMM1: [cnt_e,1024] x W1^T -> H (bias+relu, fp16 hi/lo), tensor cores
    dim3 g1(N_TOK / BM, FDIM / BN, NEXP);   // x=mt, y=nt, z=e
    mma_gemm_kernel<<<g1, 512, SMEM_BYTES>>>(1, FDIM, DDIM, b1);

    // GEMM2: [cnt_e,4096] x W2^T -> Y fp32
    dim3 g2(N_TOK / BM, DDIM / BN, NEXP);   // (32, 8, 8)
    mma_gemm_kernel<<<g2, 512, SMEM_BYTES>>>(0, DDIM, FDIM, b2);

    ln_kernel<<<N_TOK, 256>>>(tgt, gamma, beta, out);
}

// round 13
// speedup vs baseline: 1.5117x; 1.5117x over previous
#include <cuda_runtime.h>
#include <cuda_fp16.h>
#include <math.h>
#include <stdint.h>

#define N_TOK 4096      // B*S
#define DDIM  1024      // D
#define FDIM  4096      // F
#define NEXP  8         // E
#define LN_EPS 1e-5f

#define BM 128
#define BN 128
#define BK 32
#define ROWB 80                  // smem bytes per row: 32 fp16 + 8 pad
#define ATILE (128 * ROWB)       // 10240 B per operand tile
// NOTE: stage holds only 3 live tiles (Ah, Al, B) but is padded to 4*ATILE so
// SMEM_BYTES stays 122880 -> exactly 1 CTA/SM, identical occupancy to R11.
#define STAGEB (4 * ATILE)       // 40960 B per stage (4th slot unused pad)
#define NSTAGE 3
#define SMEM_BYTES (NSTAGE * STAGEB)  // 122880 B

// ---- static device scratch (no runtime allocation allowed) ----
__device__ int   g_counts[NEXP];
__device__ int   g_rows[NEXP * N_TOK];          // value = token*2 + slot
__device__ float g_slotw[2 * N_TOK];            // softmax weight per slot
__device__ __half g_Xhi[N_TOK * DDIM];
__device__ __half g_Xlo[N_TOK * DDIM];
__device__ __half g_W1[NEXP * FDIM * DDIM];     // weights: single fp16
__device__ __half g_W2[NEXP * DDIM * FDIM];
__device__ __half g_Hhi[(size_t)2 * N_TOK * FDIM];
__device__ __half g_Hlo[(size_t)2 * N_TOK * FDIM];
__device__ float g_Y[(size_t)2 * N_TOK * DDIM]; // [8192][1024] H@W2^T+b2 (unweighted)

// ============================ PTX helpers ============================
static __device__ __forceinline__ void cp16(uint32_t s, const void* g) {
    asm volatile("cp.async.cg.shared.global [%0], [%1], 16;" :: "r"(s), "l"(g));
}

#define LDSM4(r0, r1, r2, r3, addr)                                           \
    asm volatile("ldmatrix.sync.aligned.m8n8.x4.shared.b16 {%0,%1,%2,%3}, [%4];" \
                 : "=r"(r0), "=r"(r1), "=r"(r2), "=r"(r3) : "r"(addr))

// fp16 inputs, fp32 accumulators (main term)
#define MMAF32(d, a, b0, b1)                                                  \
    asm volatile("mma.sync.aligned.m16n8k16.row.col.f32.f16.f16.f32 "         \
                 "{%0,%1,%2,%3}, {%4,%5,%6,%7}, {%8,%9}, {%0,%1,%2,%3};"      \
                 : "+f"((d)[0]), "+f"((d)[1]), "+f"((d)[2]), "+f"((d)[3])     \
                 : "r"((a)[0]), "r"((a)[1]), "r"((a)[2]), "r"((a)[3]),        \
                   "r"(b0), "r"(b1))

// fp16 inputs, fp16 accumulators (correction term)
#define MMAF16(d, a, b0, b1)                                                  \
    asm volatile("mma.sync.aligned.m16n8k16.row.col.f16.f16.f16.f16 "         \
                 "{%0,%1}, {%2,%3,%4,%5}, {%6,%7}, {%0,%1};"                  \
                 : "+r"((d)[0]), "+r"((d)[1])                                 \
                 : "r"((a)[0]), "r"((a)[1]), "r"((a)[2]), "r"((a)[3]),        \
                   "r"(b0), "r"(b1))

// ============================ small kernels ============================
__global__ void init_counts_kernel() {
    if (threadIdx.x < NEXP) g_counts[threadIdx.x] = 0;
}

// fp32 -> fp16 hi/lo split (activations)
__global__ void split_fp16_kernel(const float* __restrict__ src,
                                  __half* __restrict__ hi,
                                  __half* __restrict__ lo, int n) {
    int i = (blockIdx.x * blockDim.x + threadIdx.x) * 4;
    if (i >= n) return;
    float4 v = *(const float4*)(src + i);
    float vv[4] = {v.x, v.y, v.z, v.w};
    __half h[4], l[4];
#pragma unroll
    for (int j = 0; j < 4; j++) {
        h[j] = __float2half_rn(vv[j]);
        l[j] = __float2half_rn(vv[j] - __half2float(h[j]));
    }
    __half2 h0; h0.x = h[0]; h0.y = h[1];
    __half2 h1; h1.x = h[2]; h1.y = h[3];
    __half2 l0; l0.x = l[0]; l0.y = l[1];
    __half2 l1; l1.x = l[2]; l1.y = l[3];
    *(__half2*)(hi + i)     = h0;
    *(__half2*)(hi + i + 2) = h1;
    *(__half2*)(lo + i)     = l0;
    *(__half2*)(lo + i + 2) = l1;
}

// fp32 -> fp16 single convert (weights)
__global__ void cvt_fp16_kernel(const float* __restrict__ src,
                                __half* __restrict__ dst, int n) {
    int i = (blockIdx.x * blockDim.x + threadIdx.x) * 4;
    if (i >= n) return;
    float4 v = *(const float4*)(src + i);
    __half2 a; a.x = __float2half_rn(v.x); a.y = __float2half_rn(v.y);
    __half2 b; b.x = __float2half_rn(v.z); b.y = __float2half_rn(v.w);
    *(__half2*)(dst + i)     = a;
    *(__half2*)(dst + i + 2) = b;
}

// One warp per token: 8 logits, top-2, softmax, append to expert lists.
__global__ void router_kernel(const float* __restrict__ tgt,
                              const float* __restrict__ Wr,
                              const float* __restrict__ br) {
    int token = blockIdx.x * 8 + (threadIdx.x >> 5);
    int lane  = threadIdx.x & 31;
    if (token >= N_TOK) return;

    const float* x = tgt + (size_t)token * DDIM;
    float xr[32];
#pragma unroll
    for (int i = 0; i < 32; i++) xr[i] = x[lane + 32 * i];

    float logits[NEXP];
#pragma unroll
    for (int e = 0; e < NEXP; e++) {
        const float* w = Wr + e * DDIM;
        float s = 0.f;
#pragma unroll
        for (int i = 0; i < 32; i++) s += xr[i] * w[lane + 32 * i];
#pragma unroll
        for (int o = 16; o > 0; o >>= 1) s += __shfl_xor_sync(0xffffffffu, s, o);
        logits[e] = s + br[e];
    }

    if (lane == 0) {
        int i0 = 0; float v0 = logits[0];
#pragma unroll
        for (int e = 1; e < NEXP; e++) if (logits[e] > v0) { v0 = logits[e]; i0 = e; }
        int i1 = -1; float v1 = -INFINITY;
#pragma unroll
        for (int e = 0; e < NEXP; e++) if (e != i0 && logits[e] > v1) { v1 = logits[e]; i1 = e; }
        float e1  = expf(v1 - v0);
        float inv = 1.f / (1.f + e1);
        g_slotw[2 * token]     = inv;
        g_slotw[2 * token + 1] = e1 * inv;
        int p0 = atomicAdd(&g_counts[i0], 1); g_rows[i0 * N_TOK + p0] = 2 * token;
        int p1 = atomicAdd(&g_counts[i1], 1); g_rows[i1 * N_TOK + p1] = 2 * token + 1;
    }
}

// ============================ mma.sync grouped GEMM ============================
// C[m][n] = sum_k A[m][k]*B[n][k], A split fp16 hi+lo, B single fp16:
//   accM(fp32) += Ah*B ;  accC(fp16) += Al*B ;  C = accM + accC
// 512 thr = 16 warps (4 M x 4 N), warp tile 32x32, block tile 128x128, BK=32.
// 3-stage cp.async ring, ONE __syncthreads per K-chunk.
__global__ void __launch_bounds__(512, 1)
mma_gemm_kernel(int is_gemm1, int Ndim, int Kdim, const float* __restrict__ bias) {
    extern __shared__ __align__(128) char smem[];
    uint32_t sb = (uint32_t)__cvta_generic_to_shared(smem);

    int e  = blockIdx.z;
    int nt = blockIdx.y;
    int mt = blockIdx.x;     // mt fastest -> concurrent blocks share weight tile (L2)
    int cnt = g_counts[e];
    if (mt * BM >= cnt) return;

    const int* erows = g_rows + e * N_TOK;
    const __half *Ahb, *Alb, *Wb;
    if (is_gemm1) { Ahb = g_Xhi; Alb = g_Xlo; Wb = g_W1; }
    else          { Ahb = g_Hhi; Alb = g_Hlo; Wb = g_W2; }

    int tid = threadIdx.x;

    // ---- global->smem geometry: thread -> (row = tid>>2, 16B seg = tid&3) ----
    int lrow = tid >> 2;
    int seg  = tid & 3;
    int kb   = seg * 8;                      // element offset of this thread's 16B
    int mr_l = mt * BM + lrow; if (mr_l > cnt - 1) mr_l = cnt - 1;
    int arow = erows[mr_l]; if (is_gemm1) arow >>= 1;
    const __half* aph = Ahb + (size_t)arow * Kdim + kb;
    const __half* apl = Alb + (size_t)arow * Kdim + kb;
    const __half* bpw = Wb + ((size_t)e * Ndim + nt * BN + lrow) * Kdim + kb;
    uint32_t dst = (uint32_t)lrow * ROWB + seg * 16;

    // ---- fragment (ldmatrix) geometry ----
    int lane = tid & 31, wid = tid >> 5;
    int wm = wid & 3, wn = wid >> 2;         // warp tile origin (wm*32, wn*32)
    uint32_t afa = (uint32_t)(wm * 32 + (lane & 15)) * ROWB + (lane >> 4) * 16;
    uint32_t bfa = (uint32_t)(wn * 32 + (lane & 15)) * ROWB + (lane >> 4) * 16;

    float    accM[2][4][4];
    uint32_t accC[2][4][2];
#pragma unroll
    for (int mi = 0; mi < 2; mi++)
#pragma unroll
        for (int ni = 0; ni < 4; ni++) {
#pragma unroll
            for (int r = 0; r < 4; r++) accM[mi][ni][r] = 0.f;
            accC[mi][ni][0] = 0u; accC[mi][ni][1] = 0u;
        }

    auto issue = [&](int i) {
        uint32_t d = sb + (uint32_t)(i % NSTAGE) * STAGEB + dst;
        size_t ko = (size_t)i * BK;
        cp16(d,              aph + ko);
        cp16(d + ATILE,      apl + ko);
        cp16(d + 2 * ATILE,  bpw + ko);
        asm volatile("cp.async.commit_group;" ::: "memory");
    };

    int nch = Kdim / BK;
    issue(0);
    if (nch > 1) issue(1);
    for (int i = 0; i < nch; i++) {
        if (i + 1 < nch) {
            asm volatile("cp.async.wait_group 1;" ::: "memory");
        } else {
            asm volatile("cp.async.wait_group 0;" ::: "memory");
        }
        __syncthreads();   // chunk i visible; stage (i+2)%3 free for reuse
        if (i + 2 < nch) issue(i + 2);

        uint32_t bb = sb + (uint32_t)(i % NSTAGE) * STAGEB;
#pragma unroll
        for (int s = 0; s < 2; s++) {        // two k16 steps per chunk
            uint32_t aA = bb + afa + s * 32;             // Ah (then Al)
            uint32_t aB = bb + 2 * ATILE + bfa + s * 32; // B (weights)
            uint32_t af[2][4], bf[2][4];

            // Ah fragments (2) + B fragments (2)
#pragma unroll
            for (int mi = 0; mi < 2; mi++)
                LDSM4(af[mi][0], af[mi][1], af[mi][2], af[mi][3], aA + mi * 16 * ROWB);
#pragma unroll
            for (int nj = 0; nj < 2; nj++)
                LDSM4(bf[nj][0], bf[nj][1], bf[nj][2], bf[nj][3], aB + nj * 16 * ROWB);

            // main: Ah * B -> fp32 accum
#pragma unroll
            for (int mi = 0; mi < 2; mi++)
#pragma unroll
                for (int ni = 0; ni < 4; ni++)
                    MMAF32(accM[mi][ni], af[mi],
                           bf[ni >> 1][ni & 1], bf[ni >> 1][(ni & 1) + 2]);

            // Al fragments overwrite Ah slots (2)
#pragma unroll
            for (int mi = 0; mi < 2; mi++)
                LDSM4(af[mi][0], af[mi][1], af[mi][2], af[mi][3],
                      aA + ATILE + mi * 16 * ROWB);

            // corr: Al * B -> fp16 accum
#pragma unroll
            for (int mi = 0; mi < 2; mi++)
#pragma unroll
                for (int ni = 0; ni < 4; ni++)
                    MMAF16(accC[mi][ni], af[mi],
                           bf[ni >> 1][ni & 1], bf[ni >> 1][(ni & 1) + 2]);
        }
    }

    // ---- epilogue ----
    int tg = lane >> 2, tc = (lane & 3) * 2;
    const float* bbias = bias + e * Ndim + nt * BN;
    float bias_r[8];
#pragma unroll
    for (int ni = 0; ni < 4; ni++) {
        int c = wn * 32 + ni * 8 + tc;
        bias_r[2 * ni]     = __ldg(bbias + c);
        bias_r[2 * ni + 1] = __ldg(bbias + c + 1);
    }
#pragma unroll
    for (int mi = 0; mi < 2; mi++) {
#pragma unroll
        for (int half = 0; half < 2; half++) {
            int r = wm * 32 + mi * 16 + tg + half * 8;
            int mr = mt * BM + r;
            if (mr < cnt) {
                int orow = erows[mr];
#pragma unroll
                for (int ni = 0; ni < 4; ni++) {
                    int c = wn * 32 + ni * 8 + tc;
                    __half2 hc = *reinterpret_cast<__half2*>(&accC[mi][ni][half]);
                    float v0 = accM[mi][ni][half * 2]     + __low2float(hc)  + bias_r[2 * ni];
                    float v1 = accM[mi][ni][half * 2 + 1] + __high2float(hc) + bias_r[2 * ni + 1];
                    int n = nt * BN + c;
                    if (is_gemm1) {
                        v0 = fmaxf(v0, 0.f); v1 = fmaxf(v1, 0.f);
                        __half h0 = __float2half_rn(v0);
                        __half h1 = __float2half_rn(v1);
                        __half2 hh; hh.x = h0; hh.y = h1;
                        __half2 ll;
                        ll.x = __float2half_rn(v0 - __half2float(h0));
                        ll.y = __float2half_rn(v1 - __half2float(h1));
                        *(__half2*)(g_Hhi + (size_t)orow * FDIM + n) = hh;
                        *(__half2*)(g_Hlo + (size_t)orow * FDIM + n) = ll;
                    } else {
                        float2 t; t.x = v0; t.y = v1;
                        *(float2*)(g_Y + (size_t)orow * DDIM + n) = t;
                    }
                }
            }
        }
    }
}

// ============================ LN ============================
__global__ void ln_kernel(const float* __restrict__ tgt,
                          const float* __restrict__ gamma,
                          const float* __restrict__ beta,
                          float* __restrict__ out) {
    int token = blockIdx.x;
    int tid = threadIdx.x;
    __shared__ float red[8];

    float w0 = g_slotw[2 * token], w1 = g_slotw[2 * token + 1];
    const float* x  = tgt + (size_t)token * DDIM;
    const float* y0 = g_Y + (size_t)(2 * token) * DDIM;
    const float* y1 = y0 + DDIM;

    float v[4];
    float s = 0.f;
#pragma unroll
    for (int i = 0; i < 4; i++) {
        int d = tid + 256 * i;
        v[i] = x[d] + w0 * y0[d] + w1 * y1[d];
        s += v[i];
    }
#pragma unroll
    for (int o = 16; o > 0; o >>= 1) s += __shfl_xor_sync(0xffffffffu, s, o);
    if ((tid & 31) == 0) red[tid >> 5] = s;
    __syncthreads();
    float mu = (red[0] + red[1] + red[2] + red[3] + red[4] + red[5] + red[6] + red[7]) * (1.f / DDIM);

    float sq = 0.f;
#pragma unroll
    for (int i = 0; i < 4; i++) { float dv = v[i] - mu; sq += dv * dv; }
#pragma unroll
    for (int o = 16; o > 0; o >>= 1) sq += __shfl_xor_sync(0xffffffffu, sq, o);
    __syncthreads();
    if ((tid & 31) == 0) red[tid >> 5] = sq;
    __syncthreads();
    float var = (red[0] + red[1] + red[2] + red[3] + red[4] + red[5] + red[6] + red[7]) * (1.f / DDIM);
    float inv = rsqrtf(var + LN_EPS);

#pragma unroll
    for (int i = 0; i < 4; i++) {
        int d = tid + 256 * i;
        out[(size_t)token * DDIM + d] = (v[i] - mu) * inv * gamma[d] + beta[d];
    }
}

// ============================ launch ============================
extern "C" void kernel_launch(void* const* d_in, const int* in_sizes, int n_in,
                              void* d_out, int out_size) {
    const float* tgt   = (const float*)d_in[0];
    const float* Wr    = (const float*)d_in[1];
    const float* br    = (const float*)d_in[2];
    const float* W1    = (const float*)d_in[3];
    const float* b1    = (const float*)d_in[4];
    const float* W2    = (const float*)d_in[5];
    const float* b2    = (const float*)d_in[6];
    const float* gamma = (const float*)d_in[7];
    const float* beta  = (const float*)d_in[8];
    float* out = (float*)d_out;

    cudaFuncSetAttribute(mma_gemm_kernel,
                         cudaFuncAttributeMaxDynamicSharedMemorySize, SMEM_BYTES);

    init_counts_kernel<<<1, 32>>>();
    router_kernel<<<N_TOK / 8, 256>>>(tgt, Wr, br);

    // activation split + weight convert
    {
        __half *xh, *xl, *w1p, *w2p;
        cudaGetSymbolAddress((void**)&xh,  g_Xhi);
        cudaGetSymbolAddress((void**)&xl,  g_Xlo);
        cudaGetSymbolAddress((void**)&w1p, g_W1);
        cudaGetSymbolAddress((void**)&w2p, g_W2);
        int nx = N_TOK * DDIM;              // 4,194,304
        int nw = NEXP * FDIM * DDIM;        // 33,554,432
        split_fp16_kernel<<<nx / 1024, 256>>>(tgt, xh, xl, nx);
        cvt_fp16_kernel<<<nw / 1024, 256>>>(W1, w1p, nw);
        cvt_fp16_kernel<<<nw / 1024, 256>>>(W2, w2p, nw);
    }

    // GEMM1: [cnt_e,1024] x W1^T -> H (bias+relu, fp16 hi/lo), tensor cores
    dim3 g1(N_TOK / BM, FDIM / BN, NEXP);   // x=mt, y=nt, z=e
    mma_gemm_kernel<<<g1, 512, SMEM_BYTES>>>(1, FDIM, DDIM, b1);

    // GEMM2: [cnt_e,4096] x W2^T -> Y fp32
    dim3 g2(N_TOK / BM, DDIM / BN, NEXP);   // (32, 8, 8)
    mma_gemm_kernel<<<g2, 512, SMEM_BYTES>>>(0, DDIM, FDIM, b2);

    ln_kernel<<<N_TOK, 256>>>(tgt, gamma, beta, out);
}

// round 15
// speedup vs baseline: 2.4163x; 1.5985x over previous
#include <cuda_runtime.h>
#include <cuda_fp16.h>
#include <math.h>
#include <stdint.h>

#define N_TOK 4096      // B*S
#define DDIM  1024      // D
#define FDIM  4096      // F
#define NEXP  8         // E
#define LN_EPS 1e-5f

#define BM 128
#define BN 128
#define BK 32
#define ROWB 80                  // smem bytes per row: 32 fp16 + 8 pad
#define ATILE (128 * ROWB)       // 10240 B per operand tile
// Stage holds 2 live tiles (A, B) but is padded to 4*ATILE so SMEM_BYTES stays
// 122880 -> exactly 1 CTA/SM (validated in R13; avoids ptxas 64-reg squeeze).
#define STAGEB (4 * ATILE)       // 40960 B per stage (2 slots unused pad)
#define NSTAGE 3
#define SMEM_BYTES (NSTAGE * STAGEB)  // 122880 B

// ---- static device scratch (no runtime allocation allowed) ----
__device__ int   g_counts[NEXP];
__device__ int   g_rows[NEXP * N_TOK];          // value = token*2 + slot
__device__ float g_slotw[2 * N_TOK];            // softmax weight per slot
__device__ __half g_X [N_TOK * DDIM];           // activations: single fp16
__device__ __half g_W1[NEXP * FDIM * DDIM];     // weights: single fp16
__device__ __half g_W2[NEXP * DDIM * FDIM];
__device__ __half g_H [(size_t)2 * N_TOK * FDIM]; // relu(x@W1^T+b1), fp16
__device__ float g_Y[(size_t)2 * N_TOK * DDIM]; // H@W2^T+b2 (unweighted), fp32

// ============================ PTX helpers ============================
static __device__ __forceinline__ void cp16(uint32_t s, const void* g) {
    asm volatile("cp.async.cg.shared.global [%0], [%1], 16;" :: "r"(s), "l"(g));
}

#define LDSM4(r0, r1, r2, r3, addr)                                           \
    asm volatile("ldmatrix.sync.aligned.m8n8.x4.shared.b16 {%0,%1,%2,%3}, [%4];" \
                 : "=r"(r0), "=r"(r1), "=r"(r2), "=r"(r3) : "r"(addr))

// fp16 inputs, fp32 accumulators
#define MMAF32(d, a, b0, b1)                                                  \
    asm volatile("mma.sync.aligned.m16n8k16.row.col.f32.f16.f16.f32 "         \
                 "{%0,%1,%2,%3}, {%4,%5,%6,%7}, {%8,%9}, {%0,%1,%2,%3};"      \
                 : "+f"((d)[0]), "+f"((d)[1]), "+f"((d)[2]), "+f"((d)[3])     \
                 : "r"((a)[0]), "r"((a)[1]), "r"((a)[2]), "r"((a)[3]),        \
                   "r"(b0), "r"(b1))

// ============================ small kernels ============================
__global__ void init_counts_kernel() {
    if (threadIdx.x < NEXP) g_counts[threadIdx.x] = 0;
}

// fp32 -> fp16 convert
__global__ void cvt_fp16_kernel(const float* __restrict__ src,
                                __half* __restrict__ dst, int n) {
    int i = (blockIdx.x * blockDim.x + threadIdx.x) * 4;
    if (i >= n) return;
    float4 v = *(const float4*)(src + i);
    __half2 a; a.x = __float2half_rn(v.x); a.y = __float2half_rn(v.y);
    __half2 b; b.x = __float2half_rn(v.z); b.y = __float2half_rn(v.w);
    *(__half2*)(dst + i)     = a;
    *(__half2*)(dst + i + 2) = b;
}

// One warp per token: 8 logits, top-2, softmax, append to expert lists.
__global__ void router_kernel(const float* __restrict__ tgt,
                              const float* __restrict__ Wr,
                              const float* __restrict__ br) {
    int token = blockIdx.x * 8 + (threadIdx.x >> 5);
    int lane  = threadIdx.x & 31;
    if (token >= N_TOK) return;

    const float* x = tgt + (size_t)token * DDIM;
    float xr[32];
#pragma unroll
    for (int i = 0; i < 32; i++) xr[i] = x[lane + 32 * i];

    float logits[NEXP];
#pragma unroll
    for (int e = 0; e < NEXP; e++) {
        const float* w = Wr + e * DDIM;
        float s = 0.f;
#pragma unroll
        for (int i = 0; i < 32; i++) s += xr[i] * w[lane + 32 * i];
#pragma unroll
        for (int o = 16; o > 0; o >>= 1) s += __shfl_xor_sync(0xffffffffu, s, o);
        logits[e] = s + br[e];
    }

    if (lane == 0) {
        int i0 = 0; float v0 = logits[0];
#pragma unroll
        for (int e = 1; e < NEXP; e++) if (logits[e] > v0) { v0 = logits[e]; i0 = e; }
        int i1 = -1; float v1 = -INFINITY;
#pragma unroll
        for (int e = 0; e < NEXP; e++) if (e != i0 && logits[e] > v1) { v1 = logits[e]; i1 = e; }
        float e1  = expf(v1 - v0);
        float inv = 1.f / (1.f + e1);
        g_slotw[2 * token]     = inv;
        g_slotw[2 * token + 1] = e1 * inv;
        int p0 = atomicAdd(&g_counts[i0], 1); g_rows[i0 * N_TOK + p0] = 2 * token;
        int p1 = atomicAdd(&g_counts[i1], 1); g_rows[i1 * N_TOK + p1] = 2 * token + 1;
    }
}

// ============================ mma.sync grouped GEMM ============================
// C[m][n] = sum_k A[m][k]*B[n][k], A and B fp16, fp32 accumulate.
// 512 thr = 16 warps (4 M x 4 N), warp tile 32x32, block tile 128x128, BK=32.
// 3-stage cp.async ring, ONE __syncthreads per K-chunk.
__global__ void __launch_bounds__(512, 1)
mma_gemm_kernel(int is_gemm1, int Ndim, int Kdim, const float* __restrict__ bias) {
    extern __shared__ __align__(128) char smem[];
    uint32_t sb = (uint32_t)__cvta_generic_to_shared(smem);

    int e  = blockIdx.z;
    int nt = blockIdx.y;
    int mt = blockIdx.x;     // mt fastest -> concurrent blocks share weight tile (L2)
    int cnt = g_counts[e];
    if (mt * BM >= cnt) return;

    const int* erows = g_rows + e * N_TOK;
    const __half *Ab, *Wb;
    if (is_gemm1) { Ab = g_X; Wb = g_W1; }
    else          { Ab = g_H; Wb = g_W2; }

    int tid = threadIdx.x;

    // ---- global->smem geometry: thread -> (row = tid>>2, 16B seg = tid&3) ----
    int lrow = tid >> 2;
    int seg  = tid & 3;
    int kb   = seg * 8;                      // element offset of this thread's 16B
    int mr_l = mt * BM + lrow; if (mr_l > cnt - 1) mr_l = cnt - 1;
    int arow = erows[mr_l]; if (is_gemm1) arow >>= 1;
    const __half* apx = Ab + (size_t)arow * Kdim + kb;
    const __half* bpw = Wb + ((size_t)e * Ndim + nt * BN + lrow) * Kdim + kb;
    uint32_t dst = (uint32_t)lrow * ROWB + seg * 16;

    // ---- fragment (ldmatrix) geometry ----
    int lane = tid & 31, wid = tid >> 5;
    int wm = wid & 3, wn = wid >> 2;         // warp tile origin (wm*32, wn*32)
    uint32_t afa = (uint32_t)(wm * 32 + (lane & 15)) * ROWB + (lane >> 4) * 16;
    uint32_t bfa = (uint32_t)(wn * 32 + (lane & 15)) * ROWB + (lane >> 4) * 16;

    float accM[2][4][4];
#pragma unroll
    for (int mi = 0; mi < 2; mi++)
#pragma unroll
        for (int ni = 0; ni < 4; ni++)
#pragma unroll
            for (int r = 0; r < 4; r++) accM[mi][ni][r] = 0.f;

    auto issue = [&](int i) {
        uint32_t d = sb + (uint32_t)(i % NSTAGE) * STAGEB + dst;
        size_t ko = (size_t)i * BK;
        cp16(d,          apx + ko);
        cp16(d + ATILE,  bpw + ko);
        asm volatile("cp.async.commit_group;" ::: "memory");
    };

    int nch = Kdim / BK;
    issue(0);
    if (nch > 1) issue(1);
    for (int i = 0; i < nch; i++) {
        if (i + 1 < nch) {
            asm volatile("cp.async.wait_group 1;" ::: "memory");
        } else {
            asm volatile("cp.async.wait_group 0;" ::: "memory");
        }
        __syncthreads();   // chunk i visible; stage (i+2)%3 free for reuse
        if (i + 2 < nch) issue(i + 2);

        uint32_t bb = sb + (uint32_t)(i % NSTAGE) * STAGEB;
#pragma unroll
        for (int s = 0; s < 2; s++) {        // two k16 steps per chunk
            uint32_t aA = bb + afa + s * 32;           // A
            uint32_t aB = bb + ATILE + bfa + s * 32;   // B (weights)
            uint32_t af[2][4], bf[2][4];

#pragma unroll
            for (int mi = 0; mi < 2; mi++)
                LDSM4(af[mi][0], af[mi][1], af[mi][2], af[mi][3], aA + mi * 16 * ROWB);
#pragma unroll
            for (int nj = 0; nj < 2; nj++)
                LDSM4(bf[nj][0], bf[nj][1], bf[nj][2], bf[nj][3], aB + nj * 16 * ROWB);

#pragma unroll
            for (int mi = 0; mi < 2; mi++)
#pragma unroll
                for (int ni = 0; ni < 4; ni++)
                    MMAF32(accM[mi][ni], af[mi],
                           bf[ni >> 1][ni & 1], bf[ni >> 1][(ni & 1) + 2]);
        }
    }

    // ---- epilogue ----
    int tg = lane >> 2, tc = (lane & 3) * 2;
    const float* bbias = bias + e * Ndim + nt * BN;
    float bias_r[8];
#pragma unroll
    for (int ni = 0; ni < 4; ni++) {
        int c = wn * 32 + ni * 8 + tc;
        bias_r[2 * ni]     = __ldg(bbias + c);
        bias_r[2 * ni + 1] = __ldg(bbias + c + 1);
    }
#pragma unroll
    for (int mi = 0; mi < 2; mi++) {
#pragma unroll
        for (int half = 0; half < 2; half++) {
            int r = wm * 32 + mi * 16 + tg + half * 8;
            int mr = mt * BM + r;
            if (mr < cnt) {
                int orow = erows[mr];
#pragma unroll
                for (int ni = 0; ni < 4; ni++) {
                    int c = wn * 32 + ni * 8 + tc;
                    float v0 = accM[mi][ni][half * 2]     + bias_r[2 * ni];
                    float v1 = accM[mi][ni][half * 2 + 1] + bias_r[2 * ni + 1];
                    int n = nt * BN + c;
                    if (is_gemm1) {
                        v0 = fmaxf(v0, 0.f); v1 = fmaxf(v1, 0.f);
                        __half2 hh;
                        hh.x = __float2half_rn(v0);
                        hh.y = __float2half_rn(v1);
                        *(__half2*)(g_H + (size_t)orow * FDIM + n) = hh;
                    } else {
                        float2 t; t.x = v0; t.y = v1;
                        *(float2*)(g_Y + (size_t)orow * DDIM + n) = t;
                    }
                }
            }
        }
    }
}

// ============================ LN ============================
__global__ void ln_kernel(const float* __restrict__ tgt,
                          const float* __restrict__ gamma,
                          const float* __restrict__ beta,
                          float* __restrict__ out) {
    int token = blockIdx.x;
    int tid = threadIdx.x;
    __shared__ float red[8];

    float w0 = g_slotw[2 * token], w1 = g_slotw[2 * token + 1];
    const float* x  = tgt + (size_t)token * DDIM;
    const float* y0 = g_Y + (size_t)(2 * token) * DDIM;
    const float* y1 = y0 + DDIM;

    float v[4];
    float s = 0.f;
#pragma unroll
    for (int i = 0; i < 4; i++) {
        int d = tid + 256 * i;
        v[i] = x[d] + w0 * y0[d] + w1 * y1[d];
        s += v[i];
    }
#pragma unroll
    for (int o = 16; o > 0; o >>= 1) s += __shfl_xor_sync(0xffffffffu, s, o);
    if ((tid & 31) == 0) red[tid >> 5] = s;
    __syncthreads();
    float mu = (red[0] + red[1] + red[2] + red[3] + red[4] + red[5] + red[6] + red[7]) * (1.f / DDIM);

    float sq = 0.f;
#pragma unroll
    for (int i = 0; i < 4; i++) { float dv = v[i] - mu; sq += dv * dv; }
#pragma unroll
    for (int o = 16; o > 0; o >>= 1) sq += __shfl_xor_sync(0xffffffffu, sq, o);
    __syncthreads();
    if ((tid & 31) == 0) red[tid >> 5] = sq;
    __syncthreads();
    float var = (red[0] + red[1] + red[2] + red[3] + red[4] + red[5] + red[6] + red[7]) * (1.f / DDIM);
    float inv = rsqrtf(var + LN_EPS);

#pragma unroll
    for (int i = 0; i < 4; i++) {
        int d = tid + 256 * i;
        out[(size_t)token * DDIM + d] = (v[i] - mu) * inv * gamma[d] + beta[d];
    }
}

// ============================ launch ============================
extern "C" void kernel_launch(void* const* d_in, const int* in_sizes, int n_in,
                              void* d_out, int out_size) {
    const float* tgt   = (const float*)d_in[0];
    const float* Wr    = (const float*)d_in[1];
    const float* br    = (const float*)d_in[2];
    const float* W1    = (const float*)d_in[3];
    const float* b1    = (const float*)d_in[4];
    const float* W2    = (const float*)d_in[5];
    const float* b2    = (const float*)d_in[6];
    const float* gamma = (const float*)d_in[7];
    const float* beta  = (const float*)d_in[8];
    float* out = (float*)d_out;

    cudaFuncSetAttribute(mma_gemm_kernel,
                         cudaFuncAttributeMaxDynamicSharedMemorySize, SMEM_BYTES);

    init_counts_kernel<<<1, 32>>>();
    router_kernel<<<N_TOK / 8, 256>>>(tgt, Wr, br);

    // fp16 conversion of activations + weights
    {
        __half *xp, *w1p, *w2p;
        cudaGetSymbolAddress((void**)&xp,  g_X);
        cudaGetSymbolAddress((void**)&w1p, g_W1);
        cudaGetSymbolAddress((void**)&w2p, g_W2);
        int nx = N_TOK * DDIM;              // 4,194,304
        int nw = NEXP * FDIM * DDIM;        // 33,554,432
        cvt_fp16_kernel<<<nx / 1024, 256>>>(tgt, xp, nx);
        cvt_fp16_kernel<<<nw / 1024, 256>>>(W1, w1p, nw);
        cvt_fp16_kernel<<<nw / 1024, 256>>>(W2, w2p, nw);
    }

    // GEMM1: [cnt_e,1024] x W1^T -> H (bias+relu, fp16), tensor cores
    dim3 g1(N_TOK / BM, FDIM / BN, NEXP);   // x=mt, y=nt, z=e
    mma_gemm_kernel<<<g1, 512, SMEM_BYTES>>>(1, FDIM, DDIM, b1);

    // GEMM2: [cnt_e,4096] x W2^T -> Y fp32
    dim3 g2(N_TOK / BM, DDIM / BN, NEXP);   // (32, 8, 8)
    mma_gemm_kernel<<<g2, 512, SMEM_BYTES>>>(0, DDIM, FDIM, b2);

    ln_kernel<<<N_TOK, 256>>>(tgt, gamma, beta, out);
}